// round 1
// baseline (speedup 1.0000x reference)
#include <cuda_runtime.h>
#include <cstdint>
#include <math.h>

#define EPS    1e-6f
#define MARGIN 0.3f
#define DDIM   128
#define MAXB   16384
#define JSPLIT 16
#define TM     128
#define TN     64
#define PADA   132   // 128 + 4 pad: r*132 mod 32 = r*4 -> conflict-free frag loads
#define PADN   68    // 64 + 4 pad

// ---------------- scratch (no allocations allowed) ----------------
__device__ float g_beta[MAXB];            // ||n_j||^2 - 2*eps*sum(n_j)
__device__ float g_posd[MAXB];            // ||a_i - p_i + eps||
__device__ float g_pval[JSPLIT][MAXB];    // partial min values per j-slice
__device__ int   g_pidx[JSPLIT][MAXB];    // partial argmin per j-slice
__device__ float g_rowloss[MAXB];

__device__ __forceinline__ void mma_tf32(float c[4], const uint32_t a[4], const uint32_t b[2]) {
    asm volatile(
        "mma.sync.aligned.m16n8k8.row.col.f32.tf32.tf32.f32 "
        "{%0,%1,%2,%3}, {%4,%5,%6,%7}, {%8,%9}, {%0,%1,%2,%3};\n"
        : "+f"(c[0]), "+f"(c[1]), "+f"(c[2]), "+f"(c[3])
        : "r"(a[0]), "r"(a[1]), "r"(a[2]), "r"(a[3]), "r"(b[0]), "r"(b[1]));
}

__device__ __forceinline__ void cp_async16(void* dst_smem, const void* src_gmem) {
    unsigned d = (unsigned)__cvta_generic_to_shared(dst_smem);
    asm volatile("cp.async.cg.shared.global [%0], [%1], 16;\n" :: "r"(d), "l"(src_gmem));
}
__device__ __forceinline__ void cp_commit() { asm volatile("cp.async.commit_group;\n"); }

// ---------------- kernel 1: per-row stats ----------------
__global__ void prep_kernel(const float* __restrict__ anc, const float* __restrict__ pos,
                            const float* __restrict__ neg, int B) {
    int warp = (blockIdx.x * blockDim.x + threadIdx.x) >> 5;
    int lane = threadIdx.x & 31;
    if (warp >= B) return;
    const float4 a = ((const float4*)(anc + (size_t)warp * DDIM))[lane];
    const float4 p = ((const float4*)(pos + (size_t)warp * DDIM))[lane];
    const float4 n = ((const float4*)(neg + (size_t)warp * DDIM))[lane];
    float d0 = a.x - p.x + EPS, d1 = a.y - p.y + EPS, d2 = a.z - p.z + EPS, d3 = a.w - p.w + EPS;
    float pd = d0*d0 + d1*d1 + d2*d2 + d3*d3;
    float nn = n.x*n.x + n.y*n.y + n.z*n.z + n.w*n.w;
    float ns = n.x + n.y + n.z + n.w;
    #pragma unroll
    for (int off = 16; off; off >>= 1) {
        pd += __shfl_xor_sync(0xffffffffu, pd, off);
        nn += __shfl_xor_sync(0xffffffffu, nn, off);
        ns += __shfl_xor_sync(0xffffffffu, ns, off);
    }
    if (lane == 0) {
        g_posd[warp] = sqrtf(pd);
        g_beta[warp] = nn - 2.0f * EPS * ns;
    }
}

// ---------------- kernel 2: fused TF32 GEMM + per-row argmin ----------------
__global__ __launch_bounds__(256) void gemm_argmin_kernel(
    const float* __restrict__ A, const float* __restrict__ Nn, int B)
{
    extern __shared__ float smem[];
    float* As = smem;                       // [TM][PADA]
    float* Ns = As + TM * PADA;             // [2][TN][PADN]
    float* Bs = Ns + 2 * TN * PADN;         // [2][TN]  beta tiles
    float* Rv = Bs + 2 * TN;                // [TM][2]  reduce vals
    int*   Ri = (int*)(Rv + TM * 2);        // [TM][2]  reduce idx

    const int tid   = threadIdx.x;
    const int lane  = tid & 31;
    const int wid   = tid >> 5;
    const int warpM = wid >> 1;             // 0..3, 32 rows each
    const int warpN = wid & 1;              // 0..1, 32 cols each
    const int g     = lane >> 2;            // 0..7
    const int q     = lane & 3;             // 0..3

    const int jlen    = B / JSPLIT;                 // 1024
    const int rowTile = blockIdx.x / JSPLIT;
    const int js      = blockIdx.x % JSPLIT;
    const int row0    = rowTile * TM;
    const int jbase0  = js * jlen;
    const int ntilesJ = jlen / TN;                  // 16
    const int nstages = ntilesJ * 2;                // half-K stages

    // A tile (full K) via cp.async — joins the first commit group
    {
        const float4* src = (const float4*)(A + (size_t)row0 * DDIM);
        for (int i = tid; i < TM * (DDIM / 4); i += 256) {
            int r = i >> 5, f = i & 31;
            cp_async16(&As[r * PADA + f * 4], src + (size_t)r * (DDIM / 4) + f);
        }
    }

    auto prefetchN = [&](int s) {
        if (s < nstages) {
            int tile = s >> 1, half = s & 1, buf = s & 1;
            int jb = jbase0 + tile * TN;
            for (int i = tid; i < TN * 16; i += 256) {   // 64 rows x 16 float4
                int n = i >> 4, f = i & 15;
                cp_async16(&Ns[(buf * TN + n) * PADN + f * 4],
                           (const float4*)(Nn + (size_t)(jb + n) * DDIM + half * 64) + f);
            }
            if (half == 0 && tid < 16) {
                cp_async16(&Bs[(tile & 1) * TN + tid * 4], (const float4*)(g_beta + jb) + tid);
            }
        }
    };

    const float INFF = __int_as_float(0x7f800000);
    float best[4] = {INFF, INFF, INFF, INFF};
    int   bidx[4] = {0, 0, 0, 0};
    float acc[2][4][4];

    prefetchN(0); cp_commit();
    prefetchN(1); cp_commit();

    for (int s = 0; s < nstages; ++s) {
        const int buf = s & 1, tile = s >> 1, half = s & 1;
        asm volatile("cp.async.wait_group 1;\n");
        __syncthreads();

        if (half == 0) {
            #pragma unroll
            for (int rt = 0; rt < 2; ++rt)
                #pragma unroll
                for (int nt = 0; nt < 4; ++nt)
                    #pragma unroll
                    for (int c = 0; c < 4; ++c) acc[rt][nt][c] = 0.0f;
        }

        #pragma unroll
        for (int ks = 0; ks < 8; ++ks) {
            const int kA = half * 64 + ks * 8;
            const int kN = ks * 8;
            uint32_t af[2][4], bf[4][2];
            #pragma unroll
            for (int rt = 0; rt < 2; ++rt) {
                int r = warpM * 32 + rt * 16 + g;
                af[rt][0] = __float_as_uint(As[r       * PADA + kA + q]);
                af[rt][1] = __float_as_uint(As[(r + 8) * PADA + kA + q]);
                af[rt][2] = __float_as_uint(As[r       * PADA + kA + q + 4]);
                af[rt][3] = __float_as_uint(As[(r + 8) * PADA + kA + q + 4]);
            }
            #pragma unroll
            for (int nt = 0; nt < 4; ++nt) {
                int n = warpN * 32 + nt * 8 + g;
                bf[nt][0] = __float_as_uint(Ns[(buf * TN + n) * PADN + kN + q]);
                bf[nt][1] = __float_as_uint(Ns[(buf * TN + n) * PADN + kN + q + 4]);
            }
            #pragma unroll
            for (int rt = 0; rt < 2; ++rt)
                #pragma unroll
                for (int nt = 0; nt < 4; ++nt)
                    mma_tf32(acc[rt][nt], af[rt], bf[nt]);
        }
        __syncthreads();
        prefetchN(s + 2); cp_commit();

        if (half == 1) {  // tile complete -> argmin epilogue
            const int bbuf = tile & 1;
            const int jb = jbase0 + tile * TN;
            #pragma unroll
            for (int rt = 0; rt < 2; ++rt) {
                const int s0 = rt * 2, s1 = rt * 2 + 1;
                #pragma unroll
                for (int nt = 0; nt < 4; ++nt) {
                    int jc = warpN * 32 + nt * 8 + 2 * q;
                    float b0 = Bs[bbuf * TN + jc], b1 = Bs[bbuf * TN + jc + 1];
                    float v00 = fmaf(-2.0f, acc[rt][nt][0], b0);
                    float v01 = fmaf(-2.0f, acc[rt][nt][1], b1);
                    float v10 = fmaf(-2.0f, acc[rt][nt][2], b0);
                    float v11 = fmaf(-2.0f, acc[rt][nt][3], b1);
                    if (v00 < best[s0]) { best[s0] = v00; bidx[s0] = jb + jc; }
                    if (v01 < best[s0]) { best[s0] = v01; bidx[s0] = jb + jc + 1; }
                    if (v10 < best[s1]) { best[s1] = v10; bidx[s1] = jb + jc; }
                    if (v11 < best[s1]) { best[s1] = v11; bidx[s1] = jb + jc + 1; }
                }
            }
        }
    }

    // quad reduce (lanes sharing a row), tie -> smaller index (first occurrence)
    #pragma unroll
    for (int slot = 0; slot < 4; ++slot) {
        float v = best[slot]; int ix = bidx[slot];
        #pragma unroll
        for (int off = 1; off <= 2; off <<= 1) {
            float ov = __shfl_xor_sync(0xffffffffu, v, off);
            int   oi = __shfl_xor_sync(0xffffffffu, ix, off);
            if (ov < v || (ov == v && oi < ix)) { v = ov; ix = oi; }
        }
        best[slot] = v; bidx[slot] = ix;
    }
    if (q == 0) {
        #pragma unroll
        for (int slot = 0; slot < 4; ++slot) {
            int r = warpM * 32 + (slot >> 1) * 16 + (slot & 1) * 8 + g;
            Rv[r * 2 + warpN] = best[slot];
            Ri[r * 2 + warpN] = bidx[slot];
        }
    }
    __syncthreads();
    if (tid < TM) {
        float v0 = Rv[tid * 2], v1 = Rv[tid * 2 + 1];
        int   i0 = Ri[tid * 2], i1 = Ri[tid * 2 + 1];
        if (v1 < v0 || (v1 == v0 && i1 < i0)) { v0 = v1; i0 = i1; }
        g_pval[js][row0 + tid] = v0;
        g_pidx[js][row0 + tid] = i0;
    }
}

// ---------------- kernel 3: combine partials, exact neg_dist, row loss ----------------
__global__ void combine_kernel(const float* __restrict__ anc, const float* __restrict__ neg, int B) {
    int warp = (blockIdx.x * blockDim.x + threadIdx.x) >> 5;
    int lane = threadIdx.x & 31;
    if (warp >= B) return;
    const float INFF = __int_as_float(0x7f800000);
    float v = INFF; int ix = 0x7fffffff;
    if (lane < JSPLIT) { v = g_pval[lane][warp]; ix = g_pidx[lane][warp]; }
    #pragma unroll
    for (int off = 16; off; off >>= 1) {
        float ov = __shfl_xor_sync(0xffffffffu, v, off);
        int   oi = __shfl_xor_sync(0xffffffffu, ix, off);
        if (ov < v || (ov == v && oi < ix)) { v = ov; ix = oi; }
    }
    // exact fp32 distance to the selected hard negative
    const float4 a = ((const float4*)(anc + (size_t)warp * DDIM))[lane];
    const float4 n = ((const float4*)(neg + (size_t)ix * DDIM))[lane];
    float d0 = a.x - n.x + EPS, d1 = a.y - n.y + EPS, d2 = a.z - n.z + EPS, d3 = a.w - n.w + EPS;
    float nd = d0*d0 + d1*d1 + d2*d2 + d3*d3;
    #pragma unroll
    for (int off = 16; off; off >>= 1) nd += __shfl_xor_sync(0xffffffffu, nd, off);
    if (lane == 0) {
        float t = g_posd[warp] - sqrtf(nd) + MARGIN;
        g_rowloss[warp] = t > 0.0f ? t : 0.0f;
    }
}

// ---------------- kernel 4: deterministic mean ----------------
__global__ void final_kernel(float* __restrict__ out, int B) {
    __shared__ float sm[256];
    float s = 0.0f;
    for (int i = threadIdx.x; i < B; i += 256) s += g_rowloss[i];
    sm[threadIdx.x] = s;
    __syncthreads();
    for (int w = 128; w; w >>= 1) {
        if (threadIdx.x < w) sm[threadIdx.x] += sm[threadIdx.x + w];
        __syncthreads();
    }
    if (threadIdx.x == 0) out[0] = sm[0] / (float)B;
}

// ---------------- launch ----------------
extern "C" void kernel_launch(void* const* d_in, const int* in_sizes, int n_in,
                              void* d_out, int out_size) {
    const float* anc = (const float*)d_in[0];
    const float* pos = (const float*)d_in[1];
    const float* neg = (const float*)d_in[2];
    int B = in_sizes[0] / DDIM;
    float* out = (float*)d_out;

    const int smemBytes = (TM * PADA + 2 * TN * PADN + 2 * TN + TM * 2) * 4 + TM * 2 * 4;
    cudaFuncSetAttribute(gemm_argmin_kernel, cudaFuncAttributeMaxDynamicSharedMemorySize, smemBytes);

    prep_kernel<<<(B + 7) / 8, 256>>>(anc, pos, neg, B);
    gemm_argmin_kernel<<<(B / TM) * JSPLIT, 256, smemBytes>>>(anc, neg, B);
    combine_kernel<<<(B + 7) / 8, 256>>>(anc, neg, B);
    final_kernel<<<1, 256>>>(out, B);
}

// round 3
// speedup vs baseline: 1.9550x; 1.9550x over previous
#include <cuda_runtime.h>
#include <cuda_fp16.h>
#include <cstdint>
#include <math.h>

#define EPS    1e-6f
#define MARGIN 0.3f
#define DDIM   128
#define MAXB   16384
#define JSPLIT 16
#define TM     128      // anchor rows per CTA
#define TNT    128      // negatives per tile
#define PADH   136      // halfs per smem row (128 + 8) -> conflict-free quads

// ---------------- scratch (no allocations allowed) ----------------
__device__ __align__(16) __half g_Ah[MAXB * DDIM];   // fp16 anchor
__device__ __align__(16) __half g_Nh[MAXB * DDIM];   // fp16 negative
__device__ __align__(16) float  g_beta[MAXB];        // ||n||^2 - 2*eps*sum(n)
__device__ float g_posd[MAXB];
__device__ float g_pval[JSPLIT][MAXB];
__device__ int   g_pidx[JSPLIT][MAXB];
__device__ float g_rowloss[MAXB];

// ---------------- smem layout (bytes) ----------------
#define OFF_RED_V  0                        // float[128][2]
#define OFF_RED_I  1024                     // int[128][2]
#define OFF_BS     2048                     // float[4][128] beta ring
#define OFF_A      4096                     // __half[128][PADH]   (34816 B)
#define OFF_N      38912                    // __half[2][128][PADH] (69632 B)
#define SMEM_TOTAL 108544

__device__ __forceinline__ void mma_f16(float c[4], const uint32_t a[4], const uint32_t b[2]) {
    asm volatile(
        "mma.sync.aligned.m16n8k16.row.col.f32.f16.f16.f32 "
        "{%0,%1,%2,%3}, {%4,%5,%6,%7}, {%8,%9}, {%0,%1,%2,%3};\n"
        : "+f"(c[0]), "+f"(c[1]), "+f"(c[2]), "+f"(c[3])
        : "r"(a[0]), "r"(a[1]), "r"(a[2]), "r"(a[3]), "r"(b[0]), "r"(b[1]));
}

__device__ __forceinline__ void cp_async16(void* dst_smem, const void* src_gmem) {
    unsigned d = (unsigned)__cvta_generic_to_shared(dst_smem);
    asm volatile("cp.async.cg.shared.global [%0], [%1], 16;\n" :: "r"(d), "l"(src_gmem));
}
__device__ __forceinline__ void cp_commit() { asm volatile("cp.async.commit_group;\n"); }

// ---------------- kernel 1: per-row stats + fp16 conversion ----------------
__global__ void prep_kernel(const float* __restrict__ anc, const float* __restrict__ pos,
                            const float* __restrict__ neg, int B) {
    int warp = (blockIdx.x * blockDim.x + threadIdx.x) >> 5;
    int lane = threadIdx.x & 31;
    if (warp >= B) return;
    const float4 a = ((const float4*)(anc + (size_t)warp * DDIM))[lane];
    const float4 p = ((const float4*)(pos + (size_t)warp * DDIM))[lane];
    const float4 n = ((const float4*)(neg + (size_t)warp * DDIM))[lane];

    // fp16 copies for the mining GEMM
    __half2* ah = (__half2*)(g_Ah + (size_t)warp * DDIM);
    __half2* nh = (__half2*)(g_Nh + (size_t)warp * DDIM);
    ah[lane * 2]     = __floats2half2_rn(a.x, a.y);
    ah[lane * 2 + 1] = __floats2half2_rn(a.z, a.w);
    nh[lane * 2]     = __floats2half2_rn(n.x, n.y);
    nh[lane * 2 + 1] = __floats2half2_rn(n.z, n.w);

    float d0 = a.x - p.x + EPS, d1 = a.y - p.y + EPS, d2 = a.z - p.z + EPS, d3 = a.w - p.w + EPS;
    float pd = d0*d0 + d1*d1 + d2*d2 + d3*d3;
    float nn = n.x*n.x + n.y*n.y + n.z*n.z + n.w*n.w;
    float ns = n.x + n.y + n.z + n.w;
    #pragma unroll
    for (int off = 16; off; off >>= 1) {
        pd += __shfl_xor_sync(0xffffffffu, pd, off);
        nn += __shfl_xor_sync(0xffffffffu, nn, off);
        ns += __shfl_xor_sync(0xffffffffu, ns, off);
    }
    if (lane == 0) {
        g_posd[warp] = sqrtf(pd);
        g_beta[warp] = nn - 2.0f * EPS * ns;
    }
}

// ---------------- kernel 2: fp16 GEMM + fused per-row argmin ----------------
__global__ void __launch_bounds__(256, 2) gemm_argmin_kernel(int B) {
    extern __shared__ char smem[];
    __half* As = (__half*)(smem + OFF_A);           // [128][PADH]
    __half* Ns = (__half*)(smem + OFF_N);           // [2][128][PADH]
    float*  Bs = (float*)(smem + OFF_BS);           // [4][128]
    float*  Rv = (float*)(smem + OFF_RED_V);
    int*    Ri = (int*)(smem + OFF_RED_I);

    const int tid = threadIdx.x, lane = tid & 31, wid = tid >> 5;
    const int warpM = wid >> 1;                     // 0..3 (32 rows each)
    const int warpN = wid & 1;                      // 0..1 (64 cols each)
    const int g = lane >> 2, q = lane & 3;

    const int jlen   = B / JSPLIT;                  // 1024
    const int rowT   = blockIdx.x / JSPLIT;
    const int js     = blockIdx.x % JSPLIT;
    const int row0   = rowT * TM;
    const int jbase0 = js * jlen;
    const int ntiles = jlen / TNT;                  // 8

    auto load_A = [&]() {
        for (int i = tid; i < TM * 16; i += 256) {
            int r = i >> 4, f = i & 15;
            cp_async16(As + r * PADH + f * 8, g_Ah + (size_t)(row0 + r) * DDIM + f * 8);
        }
    };
    auto load_N = [&](int buf, int tile) {
        const int jb = jbase0 + tile * TNT;
        __half* dst = Ns + buf * TNT * PADH;
        for (int i = tid; i < TNT * 16; i += 256) {
            int r = i >> 4, f = i & 15;
            cp_async16(dst + r * PADH + f * 8, g_Nh + (size_t)(jb + r) * DDIM + f * 8);
        }
        if (tid < 32)
            cp_async16(Bs + (tile & 3) * 128 + tid * 4, g_beta + jb + tid * 4);
    };

    load_A(); load_N(0, 0); cp_commit();
    load_N(1, 1); cp_commit();

    const float INFF = __int_as_float(0x7f800000);
    float best[4] = {INFF, INFF, INFF, INFF};
    int   bidx[4] = {0, 0, 0, 0};

    for (int t = 0; t < ntiles; ++t) {
        const int buf = t & 1;
        asm volatile("cp.async.wait_group 1;\n");
        __syncthreads();

        float acc[2][8][4];
        #pragma unroll
        for (int rt = 0; rt < 2; ++rt)
            #pragma unroll
            for (int nt = 0; nt < 8; ++nt)
                #pragma unroll
                for (int c = 0; c < 4; ++c) acc[rt][nt][c] = 0.0f;

        const __half* nb = Ns + buf * TNT * PADH;
        #pragma unroll
        for (int kk = 0; kk < 8; ++kk) {
            const int kb = kk * 16;
            uint32_t af[2][4], bf[8][2];
            #pragma unroll
            for (int rt = 0; rt < 2; ++rt) {
                int r = warpM * 32 + rt * 16 + g;
                const __half* a0 = As + r * PADH + kb + 2 * q;
                const __half* a1 = As + (r + 8) * PADH + kb + 2 * q;
                af[rt][0] = *(const uint32_t*)a0;
                af[rt][1] = *(const uint32_t*)a1;
                af[rt][2] = *(const uint32_t*)(a0 + 8);
                af[rt][3] = *(const uint32_t*)(a1 + 8);
            }
            #pragma unroll
            for (int nt = 0; nt < 8; ++nt) {
                int n = warpN * 64 + nt * 8 + g;
                const __half* bp = nb + n * PADH + kb + 2 * q;
                bf[nt][0] = *(const uint32_t*)bp;
                bf[nt][1] = *(const uint32_t*)(bp + 8);
            }
            #pragma unroll
            for (int rt = 0; rt < 2; ++rt)
                #pragma unroll
                for (int nt = 0; nt < 8; ++nt)
                    mma_f16(acc[rt][nt], af[rt], bf[nt]);
        }
        __syncthreads();

        if (t + 2 < ntiles) load_N(buf, t + 2);
        cp_commit();

        // epilogue: fold beta, running argmin (overlaps next tile's cp.async)
        const float* bsp = Bs + (t & 3) * 128;
        const int jb = jbase0 + t * TNT;
        #pragma unroll
        for (int rt = 0; rt < 2; ++rt) {
            const int s0 = rt * 2, s1 = rt * 2 + 1;
            #pragma unroll
            for (int nt = 0; nt < 8; ++nt) {
                int jc = warpN * 64 + nt * 8 + 2 * q;
                float b0 = bsp[jc], b1 = bsp[jc + 1];
                float v00 = fmaf(-2.0f, acc[rt][nt][0], b0);
                float v01 = fmaf(-2.0f, acc[rt][nt][1], b1);
                float v10 = fmaf(-2.0f, acc[rt][nt][2], b0);
                float v11 = fmaf(-2.0f, acc[rt][nt][3], b1);
                if (v00 < best[s0]) { best[s0] = v00; bidx[s0] = jb + jc; }
                if (v01 < best[s0]) { best[s0] = v01; bidx[s0] = jb + jc + 1; }
                if (v10 < best[s1]) { best[s1] = v10; bidx[s1] = jb + jc; }
                if (v11 < best[s1]) { best[s1] = v11; bidx[s1] = jb + jc + 1; }
            }
        }
    }

    // quad reduce (lanes sharing a row), tie -> smaller index
    #pragma unroll
    for (int slot = 0; slot < 4; ++slot) {
        float v = best[slot]; int ix = bidx[slot];
        #pragma unroll
        for (int off = 1; off <= 2; off <<= 1) {
            float ov = __shfl_xor_sync(0xffffffffu, v, off);
            int   oi = __shfl_xor_sync(0xffffffffu, ix, off);
            if (ov < v || (ov == v && oi < ix)) { v = ov; ix = oi; }
        }
        best[slot] = v; bidx[slot] = ix;
    }
    if (q == 0) {
        #pragma unroll
        for (int slot = 0; slot < 4; ++slot) {
            int r = warpM * 32 + (slot >> 1) * 16 + (slot & 1) * 8 + g;
            Rv[r * 2 + warpN] = best[slot];
            Ri[r * 2 + warpN] = bidx[slot];
        }
    }
    __syncthreads();
    if (tid < TM) {
        float v0 = Rv[tid * 2], v1 = Rv[tid * 2 + 1];
        int   i0 = Ri[tid * 2], i1 = Ri[tid * 2 + 1];
        if (v1 < v0 || (v1 == v0 && i1 < i0)) { v0 = v1; i0 = i1; }
        g_pval[js][row0 + tid] = v0;
        g_pidx[js][row0 + tid] = i0;
    }
}

// ---------------- kernel 3: combine partials, exact fp32 neg_dist, row loss ----------------
__global__ void combine_kernel(const float* __restrict__ anc, const float* __restrict__ neg, int B) {
    int warp = (blockIdx.x * blockDim.x + threadIdx.x) >> 5;
    int lane = threadIdx.x & 31;
    if (warp >= B) return;
    const float INFF = __int_as_float(0x7f800000);
    float v = INFF; int ix = 0x7fffffff;
    if (lane < JSPLIT) { v = g_pval[lane][warp]; ix = g_pidx[lane][warp]; }
    #pragma unroll
    for (int off = 16; off; off >>= 1) {
        float ov = __shfl_xor_sync(0xffffffffu, v, off);
        int   oi = __shfl_xor_sync(0xffffffffu, ix, off);
        if (ov < v || (ov == v && oi < ix)) { v = ov; ix = oi; }
    }
    const float4 a = ((const float4*)(anc + (size_t)warp * DDIM))[lane];
    const float4 n = ((const float4*)(neg + (size_t)ix * DDIM))[lane];
    float d0 = a.x - n.x + EPS, d1 = a.y - n.y + EPS, d2 = a.z - n.z + EPS, d3 = a.w - n.w + EPS;
    float nd = d0*d0 + d1*d1 + d2*d2 + d3*d3;
    #pragma unroll
    for (int off = 16; off; off >>= 1) nd += __shfl_xor_sync(0xffffffffu, nd, off);
    if (lane == 0) {
        float t = g_posd[warp] - sqrtf(nd) + MARGIN;
        g_rowloss[warp] = t > 0.0f ? t : 0.0f;
    }
}

// ---------------- kernel 4: deterministic mean ----------------
__global__ void final_kernel(float* __restrict__ out, int B) {
    __shared__ float sm[256];
    float s = 0.0f;
    for (int i = threadIdx.x; i < B; i += 256) s += g_rowloss[i];
    sm[threadIdx.x] = s;
    __syncthreads();
    for (int w = 128; w; w >>= 1) {
        if (threadIdx.x < w) sm[threadIdx.x] += sm[threadIdx.x + w];
        __syncthreads();
    }
    if (threadIdx.x == 0) out[0] = sm[0] / (float)B;
}

// ---------------- launch ----------------
extern "C" void kernel_launch(void* const* d_in, const int* in_sizes, int n_in,
                              void* d_out, int out_size) {
    const float* anc = (const float*)d_in[0];
    const float* pos = (const float*)d_in[1];
    const float* neg = (const float*)d_in[2];
    int B = in_sizes[0] / DDIM;
    float* out = (float*)d_out;

    cudaFuncSetAttribute(gemm_argmin_kernel, cudaFuncAttributeMaxDynamicSharedMemorySize, SMEM_TOTAL);

    prep_kernel<<<(B + 7) / 8, 256>>>(anc, pos, neg, B);
    gemm_argmin_kernel<<<(B / TM) * JSPLIT, 256, SMEM_TOTAL>>>(B);
    combine_kernel<<<(B + 7) / 8, 256>>>(anc, neg, B);
    final_kernel<<<1, 256>>>(out, B);
}